// round 4
// baseline (speedup 1.0000x reference)
#include <cuda_runtime.h>

#define NN 80000
#define EE 1280000
#define GG 512
#define HD 64
#define NCLS 10

// Scratch (static device globals — allowed; 16B aligned for float4)
__device__ __align__(16) float g_agg[NN * HD];
__device__ __align__(16) float g_h1[NN * HD];
__device__ __align__(16) float g_h2[NN * HD];
__device__ __align__(16) float g_pooled[GG * HD];
__device__ float g_counts[GG];

// ---------------------------------------------------------------------------
__global__ void zero_agg_kernel() {
    int i = blockIdx.x * blockDim.x + threadIdx.x;
    if (i < NN * HD / 4)
        ((float4*)g_agg)[i] = make_float4(0.f, 0.f, 0.f, 0.f);
}

__global__ void zero_pool_kernel() {
    int i = blockIdx.x * blockDim.x + threadIdx.x;
    if (i < GG * HD) g_pooled[i] = 0.f;
    if (i < GG) g_counts[i] = 0.f;
}

// ---------------------------------------------------------------------------
// Edge scatter: g_agg[dst] += src_row.  16 threads/edge, float4 per thread.
// edge_index is INT32 (JAX default x64-disabled downcasts the reference's
// "int64" to int32). selIn: 0 = external x, 1 = g_h1, 2 = g_h2.
__global__ void scatter_kernel(int selIn, const float* __restrict__ x_arg,
                               const int* __restrict__ ei) {
    const float* src = (selIn == 0) ? x_arg : ((selIn == 1) ? g_h1 : g_h2);
    int idx = blockIdx.x * blockDim.x + threadIdx.x;
    if (idx >= EE * 16) return;
    int e = idx >> 4;
    int q = idx & 15;
    int s = ei[e];
    int d = ei[EE + e];
    if ((unsigned)s >= NN || (unsigned)d >= NN) return;  // dtype-surprise guard
    float4 v = ((const float4*)src)[s * 16 + q];
    float* base = g_agg + d * 64 + q * 4;
    atomicAdd(base + 0, v.x);
    atomicAdd(base + 1, v.y);
    atomicAdd(base + 2, v.z);
    atomicAdd(base + 3, v.w);
}

// ---------------------------------------------------------------------------
// Dense: out = maybe_relu(g_agg @ Wrel^T + b + xin @ Wroot^T)
// 256 threads, 32 nodes/block. Static smem: 32KB weights + 8KB tile = 40KB.
// Two phases over the same tile buffer: phase 0 = x @ Wroot, phase 1 = agg @ Wrel.
__global__ void dense_kernel(int selIn, const float* __restrict__ x_arg,
                             int selOut,
                             const float* __restrict__ wrel,
                             const float* __restrict__ brel,
                             const float* __restrict__ wroot,
                             int relu) {
    __shared__ float sW[2][64 * 64];   // [0]=Wroot^T, [1]=Wrel^T (k-major)
    __shared__ float sT[32 * 64];      // node tile (x, then agg)

    const float* xin = (selIn == 0) ? x_arg : ((selIn == 1) ? g_h1 : g_h2);
    float* out = (selOut == 1) ? g_h1 : g_h2;

    int tid = threadIdx.x;
    int nodeBase = blockIdx.x * 32;

    // Load both weight matrices transposed: sW[.][k*64+j] = w[j*64+k]
    for (int i = tid; i < 4096; i += 256) {
        int j = i >> 6, k = i & 63;
        sW[0][k * 64 + j] = wroot[i];
        sW[1][k * 64 + j] = wrel[i];
    }

    // Phase 0 tile: x rows (contiguous copy, float4)
    {
        const float4* src = (const float4*)(xin + nodeBase * 64);
        float4* dst = (float4*)sT;
        for (int i = tid; i < 512; i += 256) dst[i] = src[i];
    }
    __syncthreads();

    int jg = tid & 15;     // 16 j-groups of 4
    int ng = tid >> 4;     // 16 node-groups of 2
    int j0 = jg * 4;
    int n0 = ng * 2;

    float4 acc0 = *(const float4*)(brel + j0);
    float4 acc1 = acc0;

#pragma unroll 8
    for (int k = 0; k < 64; k++) {
        float4 w = *(float4*)(&sW[0][k * 64 + j0]);
        float a0 = sT[n0 * 64 + k];
        float a1 = sT[(n0 + 1) * 64 + k];
        acc0.x = fmaf(a0, w.x, acc0.x); acc1.x = fmaf(a1, w.x, acc1.x);
        acc0.y = fmaf(a0, w.y, acc0.y); acc1.y = fmaf(a1, w.y, acc1.y);
        acc0.z = fmaf(a0, w.z, acc0.z); acc1.z = fmaf(a1, w.z, acc1.z);
        acc0.w = fmaf(a0, w.w, acc0.w); acc1.w = fmaf(a1, w.w, acc1.w);
    }
    __syncthreads();

    // Phase 1 tile: agg rows
    {
        const float4* src = (const float4*)(g_agg + nodeBase * 64);
        float4* dst = (float4*)sT;
        for (int i = tid; i < 512; i += 256) dst[i] = src[i];
    }
    __syncthreads();

#pragma unroll 8
    for (int k = 0; k < 64; k++) {
        float4 w = *(float4*)(&sW[1][k * 64 + j0]);
        float a0 = sT[n0 * 64 + k];
        float a1 = sT[(n0 + 1) * 64 + k];
        acc0.x = fmaf(a0, w.x, acc0.x); acc1.x = fmaf(a1, w.x, acc1.x);
        acc0.y = fmaf(a0, w.y, acc0.y); acc1.y = fmaf(a1, w.y, acc1.y);
        acc0.z = fmaf(a0, w.z, acc0.z); acc1.z = fmaf(a1, w.z, acc1.z);
        acc0.w = fmaf(a0, w.w, acc0.w); acc1.w = fmaf(a1, w.w, acc1.w);
    }

    if (relu) {
        acc0.x = fmaxf(acc0.x, 0.f); acc0.y = fmaxf(acc0.y, 0.f);
        acc0.z = fmaxf(acc0.z, 0.f); acc0.w = fmaxf(acc0.w, 0.f);
        acc1.x = fmaxf(acc1.x, 0.f); acc1.y = fmaxf(acc1.y, 0.f);
        acc1.z = fmaxf(acc1.z, 0.f); acc1.w = fmaxf(acc1.w, 0.f);
    }
    *(float4*)(out + (nodeBase + n0) * 64 + j0) = acc0;
    *(float4*)(out + (nodeBase + n0 + 1) * 64 + j0) = acc1;
}

// ---------------------------------------------------------------------------
// Pool: batch is SORTED (int32) -> run-length accumulate, flush on change.
// Reads final node features from g_h1.
__global__ void pool_kernel(const int* __restrict__ batch) {
    int nb = gridDim.x;
    int chunk = (NN + nb - 1) / nb;
    int start = blockIdx.x * chunk;
    int end = min(start + chunk, NN);
    if (start >= end) return;
    int d = threadIdx.x;

    int cur = batch[start];
    float acc = 0.f;
    float cnt = 0.f;
    for (int n = start; n < end; n++) {
        int b = batch[n];
        if (b != cur) {
            if ((unsigned)cur < GG) {
                atomicAdd(&g_pooled[cur * HD + d], acc);
                if (d == 0) atomicAdd(&g_counts[cur], cnt);
            }
            acc = 0.f;
            cnt = 0.f;
            cur = b;
        }
        acc += g_h1[n * HD + d];
        cnt += 1.f;
    }
    if ((unsigned)cur < GG) {
        atomicAdd(&g_pooled[cur * HD + d], acc);
        if (d == 0) atomicAdd(&g_counts[cur], cnt);
    }
}

// ---------------------------------------------------------------------------
// Head: out[g][c] = b_lin[c] + (pooled[g] . w_lin[c]) / max(count,1)
__global__ void head_kernel(const float* __restrict__ w_lin,
                            const float* __restrict__ b_lin,
                            float* __restrict__ out) {
    int g = blockIdx.x;
    int c = threadIdx.x;
    if (c >= NCLS) return;
    float inv = 1.f / fmaxf(g_counts[g], 1.f);
    float acc = 0.f;
#pragma unroll 8
    for (int k = 0; k < HD; k++)
        acc += g_pooled[g * HD + k] * w_lin[c * HD + k];
    out[g * NCLS + c] = b_lin[c] + acc * inv;
}

// ---------------------------------------------------------------------------
extern "C" void kernel_launch(void* const* d_in, const int* in_sizes, int n_in,
                              void* d_out, int out_size) {
    (void)in_sizes; (void)n_in; (void)out_size;
    const float* x = (const float*)d_in[0];
    const int* ei = (const int*)d_in[1];      // int32 (JAX x64 disabled)
    const int* batch = (const int*)d_in[2];   // int32
    const float* wr1 = (const float*)d_in[3];
    const float* br1 = (const float*)d_in[4];
    const float* wo1 = (const float*)d_in[5];
    const float* wr2 = (const float*)d_in[6];
    const float* br2 = (const float*)d_in[7];
    const float* wo2 = (const float*)d_in[8];
    const float* wr3 = (const float*)d_in[9];
    const float* br3 = (const float*)d_in[10];
    const float* wo3 = (const float*)d_in[11];
    const float* w_lin = (const float*)d_in[12];
    const float* b_lin = (const float*)d_in[13];
    float* out = (float*)d_out;

    const int zblocks = (NN * HD / 4 + 255) / 256;
    const int sblocks = (EE * 16 + 255) / 256;
    const int dblocks = NN / 32;  // 2500

    // Layer 1: x -> g_h1
    zero_agg_kernel<<<zblocks, 256>>>();
    scatter_kernel<<<sblocks, 256>>>(0, x, ei);
    dense_kernel<<<dblocks, 256>>>(0, x, 1, wr1, br1, wo1, 1);
    // Layer 2: g_h1 -> g_h2
    zero_agg_kernel<<<zblocks, 256>>>();
    scatter_kernel<<<sblocks, 256>>>(1, x, ei);
    dense_kernel<<<dblocks, 256>>>(1, x, 2, wr2, br2, wo2, 1);
    // Layer 3: g_h2 -> g_h1
    zero_agg_kernel<<<zblocks, 256>>>();
    scatter_kernel<<<sblocks, 256>>>(2, x, ei);
    dense_kernel<<<dblocks, 256>>>(2, x, 1, wr3, br3, wo3, 0);
    // Pool + head
    zero_pool_kernel<<<(GG * HD + 255) / 256, 256>>>();
    pool_kernel<<<256, 64>>>(batch);
    head_kernel<<<GG, 32>>>(w_lin, b_lin, out);
}

// round 5
// speedup vs baseline: 2.2381x; 2.2381x over previous
#include <cuda_runtime.h>

#define NN 80000
#define EE 1280000
#define GG 512
#define HD 64
#define NCLS 10

// Scratch (static device globals; 16B aligned for float4)
__device__ __align__(16) float g_agg[NN * HD];
__device__ __align__(16) float g_h1[NN * HD];
__device__ __align__(16) float g_h2[NN * HD];
__device__ __align__(16) float g_pooled[GG * HD];
__device__ float g_counts[GG];
// CSR scratch
__device__ int g_deg[NN];
__device__ int g_rowstart[NN + 1];
__device__ int g_cursor[NN];
__device__ int g_csrsrc[EE];

// ---------------------------------------------------------------------------
__global__ void zero_deg_kernel() {
    int i = blockIdx.x * blockDim.x + threadIdx.x;
    if (i < NN) g_deg[i] = 0;
    if (i < GG * HD) g_pooled[i] = 0.f;
    if (i < GG) g_counts[i] = 0.f;
}

// Histogram of destination degrees
__global__ void hist_kernel(const int* __restrict__ ei) {
    int e = blockIdx.x * blockDim.x + threadIdx.x;
    if (e >= EE) return;
    int d = ei[EE + e];
    if ((unsigned)d < NN) atomicAdd(&g_deg[d], 1);
}

// Single-block exclusive prefix scan over g_deg -> g_rowstart, g_cursor
__global__ void scan_kernel() {
    __shared__ int sSums[1024];
    int t = threadIdx.x;
    const int CH = 79;  // 1024*79 >= 80000
    int begin = t * CH;
    int end = min(begin + CH, NN);
    int s = 0;
    for (int i = begin; i < end; i++) s += g_deg[i];
    sSums[t] = s;
    __syncthreads();
    // Hillis-Steele inclusive scan
    for (int off = 1; off < 1024; off <<= 1) {
        int add = (t >= off) ? sSums[t - off] : 0;
        __syncthreads();
        sSums[t] += add;
        __syncthreads();
    }
    int run = sSums[t] - s;  // exclusive start for this chunk
    for (int i = begin; i < end; i++) {
        g_rowstart[i] = run;
        g_cursor[i] = run;
        run += g_deg[i];
    }
    if (t == 0) g_rowstart[NN] = EE;
}

// Fill CSR: slot per (dst) via int atomic cursor
__global__ void fill_kernel(const int* __restrict__ ei) {
    int e = blockIdx.x * blockDim.x + threadIdx.x;
    if (e >= EE) return;
    int s = ei[e];
    int d = ei[EE + e];
    if ((unsigned)s >= NN || (unsigned)d >= NN) return;
    int pos = atomicAdd(&g_cursor[d], 1);
    g_csrsrc[pos] = s;
}

// ---------------------------------------------------------------------------
// Gather aggregation: agg[n] = sum over neighbors src rows. 16 threads/node,
// float4 accumulator per thread. selIn: 0 = x, 1 = g_h1, 2 = g_h2.
__global__ void gather_kernel(int selIn, const float* __restrict__ x_arg) {
    const float* src = (selIn == 0) ? x_arg : ((selIn == 1) ? g_h1 : g_h2);
    int tid = blockIdx.x * blockDim.x + threadIdx.x;
    int n = tid >> 4;
    int q = tid & 15;
    if (n >= NN) return;
    int j = g_rowstart[n];
    int jend = g_rowstart[n + 1];
    float4 acc = make_float4(0.f, 0.f, 0.f, 0.f);
    const float4* s4 = (const float4*)src;
    // 2-way unrolled for memory-level parallelism
    for (; j + 1 < jend; j += 2) {
        int sa = g_csrsrc[j];
        int sb = g_csrsrc[j + 1];
        float4 va = s4[sa * 16 + q];
        float4 vb = s4[sb * 16 + q];
        acc.x += va.x; acc.y += va.y; acc.z += va.z; acc.w += va.w;
        acc.x += vb.x; acc.y += vb.y; acc.z += vb.z; acc.w += vb.w;
    }
    if (j < jend) {
        int sa = g_csrsrc[j];
        float4 va = s4[sa * 16 + q];
        acc.x += va.x; acc.y += va.y; acc.z += va.z; acc.w += va.w;
    }
    ((float4*)g_agg)[n * 16 + q] = acc;
}

// ---------------------------------------------------------------------------
// Dense: out = maybe_relu(g_agg @ Wrel^T + b + xin @ Wroot^T)
// 256 threads, 32 nodes/block. Static smem 40KB.
__global__ void dense_kernel(int selIn, const float* __restrict__ x_arg,
                             int selOut,
                             const float* __restrict__ wrel,
                             const float* __restrict__ brel,
                             const float* __restrict__ wroot,
                             int relu) {
    __shared__ float sW[2][64 * 64];   // [0]=Wroot^T, [1]=Wrel^T (k-major)
    __shared__ float sT[32 * 64];

    const float* xin = (selIn == 0) ? x_arg : ((selIn == 1) ? g_h1 : g_h2);
    float* out = (selOut == 1) ? g_h1 : g_h2;

    int tid = threadIdx.x;
    int nodeBase = blockIdx.x * 32;

    for (int i = tid; i < 4096; i += 256) {
        int jj = i >> 6, k = i & 63;
        sW[0][k * 64 + jj] = wroot[i];
        sW[1][k * 64 + jj] = wrel[i];
    }
    {
        const float4* src = (const float4*)(xin + nodeBase * 64);
        float4* dst = (float4*)sT;
        for (int i = tid; i < 512; i += 256) dst[i] = src[i];
    }
    __syncthreads();

    int jg = tid & 15;
    int ng = tid >> 4;
    int j0 = jg * 4;
    int n0 = ng * 2;

    float4 acc0 = *(const float4*)(brel + j0);
    float4 acc1 = acc0;

#pragma unroll 8
    for (int k = 0; k < 64; k++) {
        float4 w = *(float4*)(&sW[0][k * 64 + j0]);
        float a0 = sT[n0 * 64 + k];
        float a1 = sT[(n0 + 1) * 64 + k];
        acc0.x = fmaf(a0, w.x, acc0.x); acc1.x = fmaf(a1, w.x, acc1.x);
        acc0.y = fmaf(a0, w.y, acc0.y); acc1.y = fmaf(a1, w.y, acc1.y);
        acc0.z = fmaf(a0, w.z, acc0.z); acc1.z = fmaf(a1, w.z, acc1.z);
        acc0.w = fmaf(a0, w.w, acc0.w); acc1.w = fmaf(a1, w.w, acc1.w);
    }
    __syncthreads();
    {
        const float4* src = (const float4*)(g_agg + nodeBase * 64);
        float4* dst = (float4*)sT;
        for (int i = tid; i < 512; i += 256) dst[i] = src[i];
    }
    __syncthreads();

#pragma unroll 8
    for (int k = 0; k < 64; k++) {
        float4 w = *(float4*)(&sW[1][k * 64 + j0]);
        float a0 = sT[n0 * 64 + k];
        float a1 = sT[(n0 + 1) * 64 + k];
        acc0.x = fmaf(a0, w.x, acc0.x); acc1.x = fmaf(a1, w.x, acc1.x);
        acc0.y = fmaf(a0, w.y, acc0.y); acc1.y = fmaf(a1, w.y, acc1.y);
        acc0.z = fmaf(a0, w.z, acc0.z); acc1.z = fmaf(a1, w.z, acc1.z);
        acc0.w = fmaf(a0, w.w, acc0.w); acc1.w = fmaf(a1, w.w, acc1.w);
    }

    if (relu) {
        acc0.x = fmaxf(acc0.x, 0.f); acc0.y = fmaxf(acc0.y, 0.f);
        acc0.z = fmaxf(acc0.z, 0.f); acc0.w = fmaxf(acc0.w, 0.f);
        acc1.x = fmaxf(acc1.x, 0.f); acc1.y = fmaxf(acc1.y, 0.f);
        acc1.z = fmaxf(acc1.z, 0.f); acc1.w = fmaxf(acc1.w, 0.f);
    }
    *(float4*)(out + (nodeBase + n0) * 64 + j0) = acc0;
    *(float4*)(out + (nodeBase + n0 + 1) * 64 + j0) = acc1;
}

// ---------------------------------------------------------------------------
// Pool: batch SORTED (int32) -> run-length accumulate, flush on change.
__global__ void pool_kernel(const int* __restrict__ batch) {
    int nb = gridDim.x;
    int chunk = (NN + nb - 1) / nb;
    int start = blockIdx.x * chunk;
    int end = min(start + chunk, NN);
    if (start >= end) return;
    int d = threadIdx.x;

    int cur = batch[start];
    float acc = 0.f;
    float cnt = 0.f;
    for (int n = start; n < end; n++) {
        int b = batch[n];
        if (b != cur) {
            if ((unsigned)cur < GG) {
                atomicAdd(&g_pooled[cur * HD + d], acc);
                if (d == 0) atomicAdd(&g_counts[cur], cnt);
            }
            acc = 0.f; cnt = 0.f; cur = b;
        }
        acc += g_h1[n * HD + d];
        cnt += 1.f;
    }
    if ((unsigned)cur < GG) {
        atomicAdd(&g_pooled[cur * HD + d], acc);
        if (d == 0) atomicAdd(&g_counts[cur], cnt);
    }
}

// ---------------------------------------------------------------------------
__global__ void head_kernel(const float* __restrict__ w_lin,
                            const float* __restrict__ b_lin,
                            float* __restrict__ out) {
    int g = blockIdx.x;
    int c = threadIdx.x;
    if (c >= NCLS) return;
    float inv = 1.f / fmaxf(g_counts[g], 1.f);
    float acc = 0.f;
#pragma unroll 8
    for (int k = 0; k < HD; k++)
        acc += g_pooled[g * HD + k] * w_lin[c * HD + k];
    out[g * NCLS + c] = b_lin[c] + acc * inv;
}

// ---------------------------------------------------------------------------
extern "C" void kernel_launch(void* const* d_in, const int* in_sizes, int n_in,
                              void* d_out, int out_size) {
    (void)in_sizes; (void)n_in; (void)out_size;
    const float* x = (const float*)d_in[0];
    const int* ei = (const int*)d_in[1];      // int32
    const int* batch = (const int*)d_in[2];   // int32
    const float* wr1 = (const float*)d_in[3];
    const float* br1 = (const float*)d_in[4];
    const float* wo1 = (const float*)d_in[5];
    const float* wr2 = (const float*)d_in[6];
    const float* br2 = (const float*)d_in[7];
    const float* wo2 = (const float*)d_in[8];
    const float* wr3 = (const float*)d_in[9];
    const float* br3 = (const float*)d_in[10];
    const float* wo3 = (const float*)d_in[11];
    const float* w_lin = (const float*)d_in[12];
    const float* b_lin = (const float*)d_in[13];
    float* out = (float*)d_out;

    const int eblocks = (EE + 255) / 256;
    const int gblocks = (NN * 16 + 255) / 256;  // 16 threads/node
    const int dblocks = NN / 32;                // 2500

    // CSR build (once per launch; reused by 3 layers)
    zero_deg_kernel<<<(NN + 255) / 256, 256>>>();
    hist_kernel<<<eblocks, 256>>>(ei);
    scan_kernel<<<1, 1024>>>();
    fill_kernel<<<eblocks, 256>>>(ei);

    // Layer 1: x -> g_h1
    gather_kernel<<<gblocks, 256>>>(0, x);
    dense_kernel<<<dblocks, 256>>>(0, x, 1, wr1, br1, wo1, 1);
    // Layer 2: g_h1 -> g_h2
    gather_kernel<<<gblocks, 256>>>(1, x);
    dense_kernel<<<dblocks, 256>>>(1, x, 2, wr2, br2, wo2, 1);
    // Layer 3: g_h2 -> g_h1
    gather_kernel<<<gblocks, 256>>>(2, x);
    dense_kernel<<<dblocks, 256>>>(2, x, 1, wr3, br3, wo3, 0);

    // Pool + head
    pool_kernel<<<256, 64>>>(batch);
    head_kernel<<<GG, 32>>>(w_lin, b_lin, out);
}

// round 11
// speedup vs baseline: 2.6918x; 1.2027x over previous
#include <cuda_runtime.h>

#define NN 80000
#define EE 1280000
#define GG 512
#define HD 64
#define NCLS 10

#define SCAN_BLKS 79   // 79 * 1024 = 80896 >= NN, 256 thr x 4 elems

// Scratch (static device globals; 16B aligned)
__device__ __align__(16) float g_agg[NN * HD];
__device__ __align__(16) float g_h1[NN * HD];
__device__ __align__(16) float g_h2[NN * HD];
__device__ __align__(16) float g_pooled[GG * HD];
__device__ float g_counts[GG];
// CSR scratch
__device__ __align__(16) int g_deg[SCAN_BLKS * 1024];     // padded, zeroed
__device__ __align__(16) int g_rowstart[NN + 4];
__device__ __align__(16) int g_cursor[SCAN_BLKS * 1024];
__device__ int g_partial[SCAN_BLKS];
__device__ int g_partbase[SCAN_BLKS];
__device__ int g_csrsrc[EE];

// ---------------------------------------------------------------------------
__global__ void zero_deg_kernel() {
    int i = blockIdx.x * blockDim.x + threadIdx.x;
    if (i < SCAN_BLKS * 1024) g_deg[i] = 0;
    if (i < GG * HD) g_pooled[i] = 0.f;
    if (i < GG) g_counts[i] = 0.f;
}

// Histogram of destination degrees
__global__ void hist_kernel(const int* __restrict__ ei) {
    int e = blockIdx.x * blockDim.x + threadIdx.x;
    if (e >= EE) return;
    int d = ei[EE + e];
    if ((unsigned)d < NN) atomicAdd(&g_deg[d], 1);
}

// Scan stage 1: per-block sums (79 blocks x 256 thr x 4 elems, coalesced int4)
__global__ void scan1_kernel() {
    __shared__ int sred[256];
    int t = threadIdx.x;
    int4 v = ((const int4*)g_deg)[blockIdx.x * 256 + t];
    int s = v.x + v.y + v.z + v.w;
    sred[t] = s;
    __syncthreads();
    for (int off = 128; off > 0; off >>= 1) {
        if (t < off) sred[t] += sred[t + off];
        __syncthreads();
    }
    if (t == 0) g_partial[blockIdx.x] = sred[0];
}

// Scan stage 2: exclusive scan of 79 partials (1 block, 128 thr)
__global__ void scan2_kernel() {
    __shared__ int sp[128];
    int t = threadIdx.x;
    sp[t] = (t < SCAN_BLKS) ? g_partial[t] : 0;
    __syncthreads();
    for (int off = 1; off < 128; off <<= 1) {
        int add = (t >= off) ? sp[t - off] : 0;
        __syncthreads();
        sp[t] += add;
        __syncthreads();
    }
    if (t < SCAN_BLKS) g_partbase[t] = sp[t] - g_partial[t];  // exclusive
    if (t == 0) g_rowstart[NN] = EE;
}

// Scan stage 3: per-block exclusive scan + writeback (coalesced int4)
__global__ void scan3_kernel() {
    __shared__ int sscan[256];
    int t = threadIdx.x;
    int idx4 = blockIdx.x * 256 + t;
    int4 v = ((const int4*)g_deg)[idx4];
    int s = v.x + v.y + v.z + v.w;
    sscan[t] = s;
    __syncthreads();
    for (int off = 1; off < 256; off <<= 1) {
        int add = (t >= off) ? sscan[t - off] : 0;
        __syncthreads();
        sscan[t] += add;
        __syncthreads();
    }
    int run = g_partbase[blockIdx.x] + sscan[t] - s;  // exclusive start
    int4 rs;
    rs.x = run;
    rs.y = run + v.x;
    rs.z = run + v.x + v.y;
    rs.w = run + v.x + v.y + v.z;
    int base = idx4 * 4;
    if (base < NN) {
        // rowstart only meaningful for < NN (rowstart[NN] set in scan2)
        if (base + 3 < NN) ((int4*)g_rowstart)[idx4] = rs;
        else {
            if (base + 0 < NN) g_rowstart[base + 0] = rs.x;
            if (base + 1 < NN) g_rowstart[base + 1] = rs.y;
            if (base + 2 < NN) g_rowstart[base + 2] = rs.z;
            if (base + 3 < NN) g_rowstart[base + 3] = rs.w;
        }
    }
    ((int4*)g_cursor)[idx4] = rs;  // padded region harmless
}

// Fill CSR
__global__ void fill_kernel(const int* __restrict__ ei) {
    int e = blockIdx.x * blockDim.x + threadIdx.x;
    if (e >= EE) return;
    int s = ei[e];
    int d = ei[EE + e];
    if ((unsigned)s >= NN || (unsigned)d >= NN) return;
    int pos = atomicAdd(&g_cursor[d], 1);
    g_csrsrc[pos] = s;
}

// ---------------------------------------------------------------------------
// Gather aggregation: agg[n] = sum of neighbor rows. 16 threads/node,
// 4-way unrolled, 2 independent accumulators for MLP.
__global__ void gather_kernel(int selIn, const float* __restrict__ x_arg) {
    const float* src = (selIn == 0) ? x_arg : ((selIn == 1) ? g_h1 : g_h2);
    int tid = blockIdx.x * blockDim.x + threadIdx.x;
    int n = tid >> 4;
    int q = tid & 15;
    if (n >= NN) return;
    int j = g_rowstart[n];
    int jend = g_rowstart[n + 1];
    const float4* s4 = (const float4*)src;
    float4 a0 = make_float4(0.f, 0.f, 0.f, 0.f);
    float4 a1 = make_float4(0.f, 0.f, 0.f, 0.f);
    for (; j + 3 < jend; j += 4) {
        int i0 = g_csrsrc[j];
        int i1 = g_csrsrc[j + 1];
        int i2 = g_csrsrc[j + 2];
        int i3 = g_csrsrc[j + 3];
        float4 v0 = s4[i0 * 16 + q];
        float4 v1 = s4[i1 * 16 + q];
        float4 v2 = s4[i2 * 16 + q];
        float4 v3 = s4[i3 * 16 + q];
        a0.x += v0.x + v1.x; a0.y += v0.y + v1.y;
        a0.z += v0.z + v1.z; a0.w += v0.w + v1.w;
        a1.x += v2.x + v3.x; a1.y += v2.y + v3.y;
        a1.z += v2.z + v3.z; a1.w += v2.w + v3.w;
    }
    for (; j < jend; j++) {
        int i0 = g_csrsrc[j];
        float4 v0 = s4[i0 * 16 + q];
        a0.x += v0.x; a0.y += v0.y; a0.z += v0.z; a0.w += v0.w;
    }
    a0.x += a1.x; a0.y += a1.y; a0.z += a1.z; a0.w += a1.w;
    ((float4*)g_agg)[n * 16 + q] = a0;
}

// ---------------------------------------------------------------------------
// Dense: out = maybe_relu(g_agg @ Wrel^T + b + xin @ Wroot^T)
__global__ void dense_kernel(int selIn, const float* __restrict__ x_arg,
                             int selOut,
                             const float* __restrict__ wrel,
                             const float* __restrict__ brel,
                             const float* __restrict__ wroot,
                             int relu) {
    __shared__ float sW[2][64 * 64];
    __shared__ float sT[32 * 64];

    const float* xin = (selIn == 0) ? x_arg : ((selIn == 1) ? g_h1 : g_h2);
    float* out = (selOut == 1) ? g_h1 : g_h2;

    int tid = threadIdx.x;
    int nodeBase = blockIdx.x * 32;

    for (int i = tid; i < 4096; i += 256) {
        int jj = i >> 6, k = i & 63;
        sW[0][k * 64 + jj] = wroot[i];
        sW[1][k * 64 + jj] = wrel[i];
    }
    {
        const float4* src = (const float4*)(xin + nodeBase * 64);
        float4* dst = (float4*)sT;
        for (int i = tid; i < 512; i += 256) dst[i] = src[i];
    }
    __syncthreads();

    int jg = tid & 15;
    int ng = tid >> 4;
    int j0 = jg * 4;
    int n0 = ng * 2;

    float4 acc0 = *(const float4*)(brel + j0);
    float4 acc1 = acc0;

#pragma unroll 8
    for (int k = 0; k < 64; k++) {
        float4 w = *(float4*)(&sW[0][k * 64 + j0]);
        float a0 = sT[n0 * 64 + k];
        float a1 = sT[(n0 + 1) * 64 + k];
        acc0.x = fmaf(a0, w.x, acc0.x); acc1.x = fmaf(a1, w.x, acc1.x);
        acc0.y = fmaf(a0, w.y, acc0.y); acc1.y = fmaf(a1, w.y, acc1.y);
        acc0.z = fmaf(a0, w.z, acc0.z); acc1.z = fmaf(a1, w.z, acc1.z);
        acc0.w = fmaf(a0, w.w, acc0.w); acc1.w = fmaf(a1, w.w, acc1.w);
    }
    __syncthreads();
    {
        const float4* src = (const float4*)(g_agg + nodeBase * 64);
        float4* dst = (float4*)sT;
        for (int i = tid; i < 512; i += 256) dst[i] = src[i];
    }
    __syncthreads();

#pragma unroll 8
    for (int k = 0; k < 64; k++) {
        float4 w = *(float4*)(&sW[1][k * 64 + j0]);
        float a0 = sT[n0 * 64 + k];
        float a1 = sT[(n0 + 1) * 64 + k];
        acc0.x = fmaf(a0, w.x, acc0.x); acc1.x = fmaf(a1, w.x, acc1.x);
        acc0.y = fmaf(a0, w.y, acc0.y); acc1.y = fmaf(a1, w.y, acc1.y);
        acc0.z = fmaf(a0, w.z, acc0.z); acc1.z = fmaf(a1, w.z, acc1.z);
        acc0.w = fmaf(a0, w.w, acc0.w); acc1.w = fmaf(a1, w.w, acc1.w);
    }

    if (relu) {
        acc0.x = fmaxf(acc0.x, 0.f); acc0.y = fmaxf(acc0.y, 0.f);
        acc0.z = fmaxf(acc0.z, 0.f); acc0.w = fmaxf(acc0.w, 0.f);
        acc1.x = fmaxf(acc1.x, 0.f); acc1.y = fmaxf(acc1.y, 0.f);
        acc1.z = fmaxf(acc1.z, 0.f); acc1.w = fmaxf(acc1.w, 0.f);
    }
    *(float4*)(out + (nodeBase + n0) * 64 + j0) = acc0;
    *(float4*)(out + (nodeBase + n0 + 1) * 64 + j0) = acc1;
}

// ---------------------------------------------------------------------------
// Pool: batch SORTED (int32) -> run-length accumulate, flush on change.
__global__ void pool_kernel(const int* __restrict__ batch) {
    int nb = gridDim.x;
    int chunk = (NN + nb - 1) / nb;
    int start = blockIdx.x * chunk;
    int end = min(start + chunk, NN);
    if (start >= end) return;
    int d = threadIdx.x;

    int cur = batch[start];
    float acc = 0.f;
    float cnt = 0.f;
    for (int n = start; n < end; n++) {
        int b = batch[n];
        if (b != cur) {
            if ((unsigned)cur < GG) {
                atomicAdd(&g_pooled[cur * HD + d], acc);
                if (d == 0) atomicAdd(&g_counts[cur], cnt);
            }
            acc = 0.f; cnt = 0.f; cur = b;
        }
        acc += g_h1[n * HD + d];
        cnt += 1.f;
    }
    if ((unsigned)cur < GG) {
        atomicAdd(&g_pooled[cur * HD + d], acc);
        if (d == 0) atomicAdd(&g_counts[cur], cnt);
    }
}

// ---------------------------------------------------------------------------
__global__ void head_kernel(const float* __restrict__ w_lin,
                            const float* __restrict__ b_lin,
                            float* __restrict__ out) {
    int g = blockIdx.x;
    int c = threadIdx.x;
    if (c >= NCLS) return;
    float inv = 1.f / fmaxf(g_counts[g], 1.f);
    float acc = 0.f;
#pragma unroll 8
    for (int k = 0; k < HD; k++)
        acc += g_pooled[g * HD + k] * w_lin[c * HD + k];
    out[g * NCLS + c] = b_lin[c] + acc * inv;
}

// ---------------------------------------------------------------------------
extern "C" void kernel_launch(void* const* d_in, const int* in_sizes, int n_in,
                              void* d_out, int out_size) {
    (void)in_sizes; (void)n_in; (void)out_size;
    const float* x = (const float*)d_in[0];
    const int* ei = (const int*)d_in[1];      // int32
    const int* batch = (const int*)d_in[2];   // int32
    const float* wr1 = (const float*)d_in[3];
    const float* br1 = (const float*)d_in[4];
    const float* wo1 = (const float*)d_in[5];
    const float* wr2 = (const float*)d_in[6];
    const float* br2 = (const float*)d_in[7];
    const float* wo2 = (const float*)d_in[8];
    const float* wr3 = (const float*)d_in[9];
    const float* br3 = (const float*)d_in[10];
    const float* wo3 = (const float*)d_in[11];
    const float* w_lin = (const float*)d_in[12];
    const float* b_lin = (const float*)d_in[13];
    float* out = (float*)d_out;

    const int eblocks = (EE + 255) / 256;
    const int gblocks = (NN * 16 + 255) / 256;
    const int dblocks = NN / 32;

    // CSR build (coalesced hierarchical scan)
    zero_deg_kernel<<<(SCAN_BLKS * 1024 + 255) / 256, 256>>>();
    hist_kernel<<<eblocks, 256>>>(ei);
    scan1_kernel<<<SCAN_BLKS, 256>>>();
    scan2_kernel<<<1, 128>>>();
    scan3_kernel<<<SCAN_BLKS, 256>>>();
    fill_kernel<<<eblocks, 256>>>(ei);

    // Layer 1: x -> g_h1
    gather_kernel<<<gblocks, 256>>>(0, x);
    dense_kernel<<<dblocks, 256>>>(0, x, 1, wr1, br1, wo1, 1);
    // Layer 2: g_h1 -> g_h2
    gather_kernel<<<gblocks, 256>>>(1, x);
    dense_kernel<<<dblocks, 256>>>(1, x, 2, wr2, br2, wo2, 1);
    // Layer 3: g_h2 -> g_h1
    gather_kernel<<<gblocks, 256>>>(2, x);
    dense_kernel<<<dblocks, 256>>>(2, x, 1, wr3, br3, wo3, 0);

    // Pool + head
    pool_kernel<<<256, 64>>>(batch);
    head_kernel<<<GG, 32>>>(w_lin, b_lin, out);
}

// round 12
// speedup vs baseline: 2.7639x; 1.0268x over previous
#include <cuda_runtime.h>

#define NN 80000
#define EE 1280000
#define GG 512
#define HD 64
#define NCLS 10

#define SCAN_BLKS 79   // 79 * 1024 = 80896 >= NN

// Scratch (static device globals; 16B aligned)
__device__ __align__(16) float g_h1[NN * HD];
__device__ __align__(16) float g_h2[NN * HD];
__device__ __align__(16) float g_pooled[GG * HD];
__device__ float g_counts[GG];
// CSR scratch
__device__ __align__(16) int g_deg[SCAN_BLKS * 1024];     // padded, zeroed
__device__ __align__(16) int g_rowstart[NN + 4];
__device__ __align__(16) int g_cursor[SCAN_BLKS * 1024];
__device__ int g_partial[SCAN_BLKS];
__device__ int g_partbase[SCAN_BLKS];
__device__ int g_csrsrc[EE];

// ---------------------------------------------------------------------------
__global__ void zero_deg_kernel() {
    int i = blockIdx.x * blockDim.x + threadIdx.x;
    if (i < SCAN_BLKS * 1024) g_deg[i] = 0;
    if (i < GG * HD) g_pooled[i] = 0.f;
    if (i < GG) g_counts[i] = 0.f;
}

// Histogram of destination degrees
__global__ void hist_kernel(const int* __restrict__ ei) {
    int e = blockIdx.x * blockDim.x + threadIdx.x;
    if (e >= EE) return;
    int d = ei[EE + e];
    if ((unsigned)d < NN) atomicAdd(&g_deg[d], 1);
}

// Scan stage 1: per-block sums (79 blocks x 256 thr x 4 elems, coalesced int4)
__global__ void scan1_kernel() {
    __shared__ int sred[256];
    int t = threadIdx.x;
    int4 v = ((const int4*)g_deg)[blockIdx.x * 256 + t];
    int s = v.x + v.y + v.z + v.w;
    sred[t] = s;
    __syncthreads();
    for (int off = 128; off > 0; off >>= 1) {
        if (t < off) sred[t] += sred[t + off];
        __syncthreads();
    }
    if (t == 0) g_partial[blockIdx.x] = sred[0];
}

// Scan stage 2: exclusive scan of 79 partials (1 block, 128 thr)
__global__ void scan2_kernel() {
    __shared__ int sp[128];
    int t = threadIdx.x;
    sp[t] = (t < SCAN_BLKS) ? g_partial[t] : 0;
    __syncthreads();
    for (int off = 1; off < 128; off <<= 1) {
        int add = (t >= off) ? sp[t - off] : 0;
        __syncthreads();
        sp[t] += add;
        __syncthreads();
    }
    if (t < SCAN_BLKS) g_partbase[t] = sp[t] - g_partial[t];  // exclusive
    if (t == 0) g_rowstart[NN] = EE;
}

// Scan stage 3: per-block exclusive scan + writeback (coalesced int4)
__global__ void scan3_kernel() {
    __shared__ int sscan[256];
    int t = threadIdx.x;
    int idx4 = blockIdx.x * 256 + t;
    int4 v = ((const int4*)g_deg)[idx4];
    int s = v.x + v.y + v.z + v.w;
    sscan[t] = s;
    __syncthreads();
    for (int off = 1; off < 256; off <<= 1) {
        int add = (t >= off) ? sscan[t - off] : 0;
        __syncthreads();
        sscan[t] += add;
        __syncthreads();
    }
    int run = g_partbase[blockIdx.x] + sscan[t] - s;  // exclusive start
    int4 rs;
    rs.x = run;
    rs.y = run + v.x;
    rs.z = run + v.x + v.y;
    rs.w = run + v.x + v.y + v.z;
    int base = idx4 * 4;
    if (base < NN) {
        if (base + 3 < NN) ((int4*)g_rowstart)[idx4] = rs;
        else {
            if (base + 0 < NN) g_rowstart[base + 0] = rs.x;
            if (base + 1 < NN) g_rowstart[base + 1] = rs.y;
            if (base + 2 < NN) g_rowstart[base + 2] = rs.z;
            if (base + 3 < NN) g_rowstart[base + 3] = rs.w;
        }
    }
    ((int4*)g_cursor)[idx4] = rs;  // padded region harmless
}

// Fill CSR
__global__ void fill_kernel(const int* __restrict__ ei) {
    int e = blockIdx.x * blockDim.x + threadIdx.x;
    if (e >= EE) return;
    int s = ei[e];
    int d = ei[EE + e];
    if ((unsigned)s >= NN || (unsigned)d >= NN) return;
    int pos = atomicAdd(&g_cursor[d], 1);
    g_csrsrc[pos] = s;
}

// ---------------------------------------------------------------------------
// FUSED layer: out = maybe_relu( (sum_neighbors in) @ Wrel^T + b + in @ Wroot^T )
// 256 threads, 32 nodes/block. smem: 32KB weights + 8KB tile = 40KB.
// Phase G: gather neighbor sums into sT (tid&15 = quarter-row q, tid>>4 = node).
// Phase A: acc = bias + sT(agg) @ Wrel^T.
// Phase X: stage x tile in sT, acc += sT(x) @ Wroot^T, relu, store.
__global__ void fused_layer_kernel(int selIn, const float* __restrict__ x_arg,
                                   int selOut,
                                   const float* __restrict__ wrel,
                                   const float* __restrict__ brel,
                                   const float* __restrict__ wroot,
                                   int relu) {
    __shared__ float sW[2][64 * 64];   // [0]=Wrel^T, [1]=Wroot^T (k-major)
    __shared__ float sT[32 * 64];

    const float* xin = (selIn == 0) ? x_arg : ((selIn == 1) ? g_h1 : g_h2);
    float* out = (selOut == 1) ? g_h1 : g_h2;

    int tid = threadIdx.x;
    int nodeBase = blockIdx.x * 32;

    // Issue weight loads early (latency overlapped with gather below)
    for (int i = tid; i < 4096; i += 256) {
        int jj = i >> 6, k = i & 63;
        sW[0][k * 64 + jj] = wrel[i];
        sW[1][k * 64 + jj] = wroot[i];
    }

    // Phase G: gather. 16 threads per node, 2 nodes per thread.
    {
        int q = tid & 15;           // quarter-row (4 floats)
        int ln = tid >> 4;          // local node 0..15; also handles ln+16
        const float4* s4 = (const float4*)xin;
#pragma unroll
        for (int half = 0; half < 2; half++) {
            int n = nodeBase + ln + half * 16;
            int j = g_rowstart[n];
            int jend = g_rowstart[n + 1];
            float4 a0 = make_float4(0.f, 0.f, 0.f, 0.f);
            float4 a1 = make_float4(0.f, 0.f, 0.f, 0.f);
            for (; j + 3 < jend; j += 4) {
                int i0 = g_csrsrc[j];
                int i1 = g_csrsrc[j + 1];
                int i2 = g_csrsrc[j + 2];
                int i3 = g_csrsrc[j + 3];
                float4 v0 = s4[i0 * 16 + q];
                float4 v1 = s4[i1 * 16 + q];
                float4 v2 = s4[i2 * 16 + q];
                float4 v3 = s4[i3 * 16 + q];
                a0.x += v0.x + v1.x; a0.y += v0.y + v1.y;
                a0.z += v0.z + v1.z; a0.w += v0.w + v1.w;
                a1.x += v2.x + v3.x; a1.y += v2.y + v3.y;
                a1.z += v2.z + v3.z; a1.w += v2.w + v3.w;
            }
            for (; j < jend; j++) {
                int i0 = g_csrsrc[j];
                float4 v0 = s4[i0 * 16 + q];
                a0.x += v0.x; a0.y += v0.y; a0.z += v0.z; a0.w += v0.w;
            }
            a0.x += a1.x; a0.y += a1.y; a0.z += a1.z; a0.w += a1.w;
            *(float4*)(&sT[(ln + half * 16) * 64 + q * 4]) = a0;
        }
    }
    __syncthreads();

    int jg = tid & 15;
    int ng = tid >> 4;
    int j0 = jg * 4;
    int n0 = ng * 2;

    float4 acc0 = *(const float4*)(brel + j0);
    float4 acc1 = acc0;

    // Phase A: agg @ Wrel^T
#pragma unroll 8
    for (int k = 0; k < 64; k++) {
        float4 w = *(float4*)(&sW[0][k * 64 + j0]);
        float a0 = sT[n0 * 64 + k];
        float a1 = sT[(n0 + 1) * 64 + k];
        acc0.x = fmaf(a0, w.x, acc0.x); acc1.x = fmaf(a1, w.x, acc1.x);
        acc0.y = fmaf(a0, w.y, acc0.y); acc1.y = fmaf(a1, w.y, acc1.y);
        acc0.z = fmaf(a0, w.z, acc0.z); acc1.z = fmaf(a1, w.z, acc1.z);
        acc0.w = fmaf(a0, w.w, acc0.w); acc1.w = fmaf(a1, w.w, acc1.w);
    }
    __syncthreads();

    // Stage x tile
    {
        const float4* src = (const float4*)(xin + nodeBase * 64);
        float4* dst = (float4*)sT;
        for (int i = tid; i < 512; i += 256) dst[i] = src[i];
    }
    __syncthreads();

    // Phase X: x @ Wroot^T
#pragma unroll 8
    for (int k = 0; k < 64; k++) {
        float4 w = *(float4*)(&sW[1][k * 64 + j0]);
        float a0 = sT[n0 * 64 + k];
        float a1 = sT[(n0 + 1) * 64 + k];
        acc0.x = fmaf(a0, w.x, acc0.x); acc1.x = fmaf(a1, w.x, acc1.x);
        acc0.y = fmaf(a0, w.y, acc0.y); acc1.y = fmaf(a1, w.y, acc1.y);
        acc0.z = fmaf(a0, w.z, acc0.z); acc1.z = fmaf(a1, w.z, acc1.z);
        acc0.w = fmaf(a0, w.w, acc0.w); acc1.w = fmaf(a1, w.w, acc1.w);
    }

    if (relu) {
        acc0.x = fmaxf(acc0.x, 0.f); acc0.y = fmaxf(acc0.y, 0.f);
        acc0.z = fmaxf(acc0.z, 0.f); acc0.w = fmaxf(acc0.w, 0.f);
        acc1.x = fmaxf(acc1.x, 0.f); acc1.y = fmaxf(acc1.y, 0.f);
        acc1.z = fmaxf(acc1.z, 0.f); acc1.w = fmaxf(acc1.w, 0.f);
    }
    *(float4*)(out + (nodeBase + n0) * 64 + j0) = acc0;
    *(float4*)(out + (nodeBase + n0 + 1) * 64 + j0) = acc1;
}

// ---------------------------------------------------------------------------
// Pool: batch SORTED (int32) -> run-length accumulate, flush on change.
__global__ void pool_kernel(const int* __restrict__ batch) {
    int nb = gridDim.x;
    int chunk = (NN + nb - 1) / nb;
    int start = blockIdx.x * chunk;
    int end = min(start + chunk, NN);
    if (start >= end) return;
    int d = threadIdx.x;

    int cur = batch[start];
    float acc = 0.f;
    float cnt = 0.f;
    for (int n = start; n < end; n++) {
        int b = batch[n];
        if (b != cur) {
            if ((unsigned)cur < GG) {
                atomicAdd(&g_pooled[cur * HD + d], acc);
                if (d == 0) atomicAdd(&g_counts[cur], cnt);
            }
            acc = 0.f; cnt = 0.f; cur = b;
        }
        acc += g_h1[n * HD + d];
        cnt += 1.f;
    }
    if ((unsigned)cur < GG) {
        atomicAdd(&g_pooled[cur * HD + d], acc);
        if (d == 0) atomicAdd(&g_counts[cur], cnt);
    }
}

// ---------------------------------------------------------------------------
__global__ void head_kernel(const float* __restrict__ w_lin,
                            const float* __restrict__ b_lin,
                            float* __restrict__ out) {
    int g = blockIdx.x;
    int c = threadIdx.x;
    if (c >= NCLS) return;
    float inv = 1.f / fmaxf(g_counts[g], 1.f);
    float acc = 0.f;
#pragma unroll 8
    for (int k = 0; k < HD; k++)
        acc += g_pooled[g * HD + k] * w_lin[c * HD + k];
    out[g * NCLS + c] = b_lin[c] + acc * inv;
}

// ---------------------------------------------------------------------------
extern "C" void kernel_launch(void* const* d_in, const int* in_sizes, int n_in,
                              void* d_out, int out_size) {
    (void)in_sizes; (void)n_in; (void)out_size;
    const float* x = (const float*)d_in[0];
    const int* ei = (const int*)d_in[1];      // int32
    const int* batch = (const int*)d_in[2];   // int32
    const float* wr1 = (const float*)d_in[3];
    const float* br1 = (const float*)d_in[4];
    const float* wo1 = (const float*)d_in[5];
    const float* wr2 = (const float*)d_in[6];
    const float* br2 = (const float*)d_in[7];
    const float* wo2 = (const float*)d_in[8];
    const float* wr3 = (const float*)d_in[9];
    const float* br3 = (const float*)d_in[10];
    const float* wo3 = (const float*)d_in[11];
    const float* w_lin = (const float*)d_in[12];
    const float* b_lin = (const float*)d_in[13];
    float* out = (float*)d_out;

    const int eblocks = (EE + 255) / 256;
    const int fblocks = NN / 32;  // 2500

    // CSR build (coalesced hierarchical scan)
    zero_deg_kernel<<<(SCAN_BLKS * 1024 + 255) / 256, 256>>>();
    hist_kernel<<<eblocks, 256>>>(ei);
    scan1_kernel<<<SCAN_BLKS, 256>>>();
    scan2_kernel<<<1, 128>>>();
    scan3_kernel<<<SCAN_BLKS, 256>>>();
    fill_kernel<<<eblocks, 256>>>(ei);

    // Fused gather+dense layers
    fused_layer_kernel<<<fblocks, 256>>>(0, x, 1, wr1, br1, wo1, 1);
    fused_layer_kernel<<<fblocks, 256>>>(1, x, 2, wr2, br2, wo2, 1);
    fused_layer_kernel<<<fblocks, 256>>>(2, x, 1, wr3, br3, wo3, 0);

    // Pool + head
    pool_kernel<<<256, 64>>>(batch);
    head_kernel<<<GG, 32>>>(w_lin, b_lin, out);
}

// round 14
// speedup vs baseline: 4.5010x; 1.6285x over previous
#include <cuda_runtime.h>

#define NN 80000
#define EE 1280000
#define GG 512
#define HD 64
#define NCLS 10

#define SCAN_BLKS 79   // 79 * 1024 = 80896 >= NN

// Scratch (static device globals; 16B aligned)
__device__ __align__(16) float g_h1[NN * HD];
__device__ __align__(16) float g_h2[NN * HD];
// CSR scratch
__device__ __align__(16) int g_deg[SCAN_BLKS * 1024];     // padded, zeroed
__device__ __align__(16) int g_rowstart[NN + 4];
__device__ __align__(16) int g_cursor[SCAN_BLKS * 1024];
__device__ int g_partial[SCAN_BLKS];
__device__ int g_partbase[SCAN_BLKS];
__device__ int g_csrsrc[EE];
__device__ int g_bnd[GG + 1];

// ---------------------------------------------------------------------------
__global__ void zero_deg_kernel() {
    int i = blockIdx.x * blockDim.x + threadIdx.x;
    if (i < SCAN_BLKS * 1024) g_deg[i] = 0;
}

// Histogram of destination degrees
__global__ void hist_kernel(const int* __restrict__ ei) {
    int e = blockIdx.x * blockDim.x + threadIdx.x;
    if (e >= EE) return;
    int d = ei[EE + e];
    if ((unsigned)d < NN) atomicAdd(&g_deg[d], 1);
}

// Graph boundaries: g_bnd[g] = lower_bound(batch, g)
__global__ void bnd_kernel(const int* __restrict__ batch) {
    int g = blockIdx.x * blockDim.x + threadIdx.x;
    if (g > GG) return;
    int lo = 0, hi = NN;
    while (lo < hi) {
        int mid = (lo + hi) >> 1;
        if (batch[mid] < g) lo = mid + 1; else hi = mid;
    }
    g_bnd[g] = lo;
}

// Scan stage 1: per-block sums (79 blocks x 256 thr x 4 elems, coalesced int4)
__global__ void scan1_kernel() {
    __shared__ int sred[256];
    int t = threadIdx.x;
    int4 v = ((const int4*)g_deg)[blockIdx.x * 256 + t];
    int s = v.x + v.y + v.z + v.w;
    sred[t] = s;
    __syncthreads();
    for (int off = 128; off > 0; off >>= 1) {
        if (t < off) sred[t] += sred[t + off];
        __syncthreads();
    }
    if (t == 0) g_partial[blockIdx.x] = sred[0];
}

// Scan stage 2: exclusive scan of 79 partials (1 block, 128 thr)
__global__ void scan2_kernel() {
    __shared__ int sp[128];
    int t = threadIdx.x;
    sp[t] = (t < SCAN_BLKS) ? g_partial[t] : 0;
    __syncthreads();
    for (int off = 1; off < 128; off <<= 1) {
        int add = (t >= off) ? sp[t - off] : 0;
        __syncthreads();
        sp[t] += add;
        __syncthreads();
    }
    if (t < SCAN_BLKS) g_partbase[t] = sp[t] - g_partial[t];  // exclusive
    if (t == 0) g_rowstart[NN] = EE;
}

// Scan stage 3: per-block exclusive scan + writeback (coalesced int4)
__global__ void scan3_kernel() {
    __shared__ int sscan[256];
    int t = threadIdx.x;
    int idx4 = blockIdx.x * 256 + t;
    int4 v = ((const int4*)g_deg)[idx4];
    int s = v.x + v.y + v.z + v.w;
    sscan[t] = s;
    __syncthreads();
    for (int off = 1; off < 256; off <<= 1) {
        int add = (t >= off) ? sscan[t - off] : 0;
        __syncthreads();
        sscan[t] += add;
        __syncthreads();
    }
    int run = g_partbase[blockIdx.x] + sscan[t] - s;  // exclusive start
    int4 rs;
    rs.x = run;
    rs.y = run + v.x;
    rs.z = run + v.x + v.y;
    rs.w = run + v.x + v.y + v.z;
    int base = idx4 * 4;
    if (base < NN) {
        if (base + 3 < NN) ((int4*)g_rowstart)[idx4] = rs;
        else {
            if (base + 0 < NN) g_rowstart[base + 0] = rs.x;
            if (base + 1 < NN) g_rowstart[base + 1] = rs.y;
            if (base + 2 < NN) g_rowstart[base + 2] = rs.z;
            if (base + 3 < NN) g_rowstart[base + 3] = rs.w;
        }
    }
    ((int4*)g_cursor)[idx4] = rs;  // padded region harmless
}

// Fill CSR
__global__ void fill_kernel(const int* __restrict__ ei) {
    int e = blockIdx.x * blockDim.x + threadIdx.x;
    if (e >= EE) return;
    int s = ei[e];
    int d = ei[EE + e];
    if ((unsigned)s >= NN || (unsigned)d >= NN) return;
    int pos = atomicAdd(&g_cursor[d], 1);
    g_csrsrc[pos] = s;
}

// ---------------------------------------------------------------------------
// FUSED layer, 64 nodes/block, 256 threads, 48KB static smem.
// Phase G: gather neighbor sums into sT (software-pipelined: prefetch next
//          4 rows while summing current 4 -> MLP ~8).
// Phase A: acc = bias + sT(agg) @ Wrel^T.
// Phase X: stage x tile, acc += sT(x) @ Wroot^T, relu, store.
__global__ void fused_layer_kernel(int selIn, const float* __restrict__ x_arg,
                                   int selOut,
                                   const float* __restrict__ wrel,
                                   const float* __restrict__ brel,
                                   const float* __restrict__ wroot,
                                   int relu) {
    __shared__ float sW[2][64 * 64];   // [0]=Wrel^T, [1]=Wroot^T (k-major)
    __shared__ float sT[64 * 64];      // 16KB node tile

    const float* xin = (selIn == 0) ? x_arg : ((selIn == 1) ? g_h1 : g_h2);
    float* out = (selOut == 1) ? g_h1 : g_h2;

    int tid = threadIdx.x;
    int nodeBase = blockIdx.x * 64;

    // Weight loads issued early; latency overlaps gather
    for (int i = tid; i < 4096; i += 256) {
        int jj = i >> 6, k = i & 63;
        sW[0][k * 64 + jj] = wrel[i];
        sW[1][k * 64 + jj] = wroot[i];
    }

    // Phase G: 16 threads/node, 4 nodes/thread, pipelined inner loop
    {
        int q = tid & 15;
        int ln = tid >> 4;
        const float4* s4 = (const float4*)xin;
#pragma unroll
        for (int half = 0; half < 4; half++) {
            int n = nodeBase + ln + half * 16;
            int jj = g_rowstart[n];
            int jend = g_rowstart[n + 1];
            float4 a0 = make_float4(0.f, 0.f, 0.f, 0.f);
            float4 a1 = make_float4(0.f, 0.f, 0.f, 0.f);
            int nfull = (jend - jj) >> 2;
            if (nfull > 0) {
                int i0 = g_csrsrc[jj], i1 = g_csrsrc[jj + 1];
                int i2 = g_csrsrc[jj + 2], i3 = g_csrsrc[jj + 3];
                float4 v0 = s4[i0 * 16 + q];
                float4 v1 = s4[i1 * 16 + q];
                float4 v2 = s4[i2 * 16 + q];
                float4 v3 = s4[i3 * 16 + q];
                for (int b = 1; b < nfull; b++) {
                    jj += 4;
                    int k0 = g_csrsrc[jj], k1 = g_csrsrc[jj + 1];
                    int k2 = g_csrsrc[jj + 2], k3 = g_csrsrc[jj + 3];
                    float4 w0 = s4[k0 * 16 + q];
                    float4 w1 = s4[k1 * 16 + q];
                    float4 w2 = s4[k2 * 16 + q];
                    float4 w3 = s4[k3 * 16 + q];
                    a0.x += v0.x + v1.x; a0.y += v0.y + v1.y;
                    a0.z += v0.z + v1.z; a0.w += v0.w + v1.w;
                    a1.x += v2.x + v3.x; a1.y += v2.y + v3.y;
                    a1.z += v2.z + v3.z; a1.w += v2.w + v3.w;
                    v0 = w0; v1 = w1; v2 = w2; v3 = w3;
                }
                a0.x += v0.x + v1.x; a0.y += v0.y + v1.y;
                a0.z += v0.z + v1.z; a0.w += v0.w + v1.w;
                a1.x += v2.x + v3.x; a1.y += v2.y + v3.y;
                a1.z += v2.z + v3.z; a1.w += v2.w + v3.w;
                jj += 4;
            }
            for (; jj < jend; jj++) {
                int i0 = g_csrsrc[jj];
                float4 v = s4[i0 * 16 + q];
                a0.x += v.x; a0.y += v.y; a0.z += v.z; a0.w += v.w;
            }
            a0.x += a1.x; a0.y += a1.y; a0.z += a1.z; a0.w += a1.w;
            *(float4*)(&sT[(ln + half * 16) * 64 + q * 4]) = a0;
        }
    }
    __syncthreads();

    int jg = tid & 15;
    int ng = tid >> 4;
    int j0 = jg * 4;
    int n0 = ng * 4;

    float4 bb = *(const float4*)(brel + j0);
    float4 acc0 = bb, acc1 = bb, acc2 = bb, acc3 = bb;

    // Phase A: agg @ Wrel^T
#pragma unroll 4
    for (int k = 0; k < 64; k++) {
        float4 w = *(float4*)(&sW[0][k * 64 + j0]);
        float a0 = sT[(n0 + 0) * 64 + k];
        float a1 = sT[(n0 + 1) * 64 + k];
        float a2 = sT[(n0 + 2) * 64 + k];
        float a3 = sT[(n0 + 3) * 64 + k];
        acc0.x = fmaf(a0, w.x, acc0.x); acc1.x = fmaf(a1, w.x, acc1.x);
        acc2.x = fmaf(a2, w.x, acc2.x); acc3.x = fmaf(a3, w.x, acc3.x);
        acc0.y = fmaf(a0, w.y, acc0.y); acc1.y = fmaf(a1, w.y, acc1.y);
        acc2.y = fmaf(a2, w.y, acc2.y); acc3.y = fmaf(a3, w.y, acc3.y);
        acc0.z = fmaf(a0, w.z, acc0.z); acc1.z = fmaf(a1, w.z, acc1.z);
        acc2.z = fmaf(a2, w.z, acc2.z); acc3.z = fmaf(a3, w.z, acc3.z);
        acc0.w = fmaf(a0, w.w, acc0.w); acc1.w = fmaf(a1, w.w, acc1.w);
        acc2.w = fmaf(a2, w.w, acc2.w); acc3.w = fmaf(a3, w.w, acc3.w);
    }
    __syncthreads();

    // Stage x tile (64 rows, contiguous float4 copy)
    {
        const float4* src = (const float4*)(xin + nodeBase * 64);
        float4* dst = (float4*)sT;
        for (int i = tid; i < 1024; i += 256) dst[i] = src[i];
    }
    __syncthreads();

    // Phase X: x @ Wroot^T
#pragma unroll 4
    for (int k = 0; k < 64; k++) {
        float4 w = *(float4*)(&sW[1][k * 64 + j0]);
        float a0 = sT[(n0 + 0) * 64 + k];
        float a1 = sT[(n0 + 1) * 64 + k];
        float a2 = sT[(n0 + 2) * 64 + k];
        float a3 = sT[(n0 + 3) * 64 + k];
        acc0.x = fmaf(a0, w.x, acc0.x); acc1.x = fmaf(a1, w.x, acc1.x);
        acc2.x = fmaf(a2, w.x, acc2.x); acc3.x = fmaf(a3, w.x, acc3.x);
        acc0.y = fmaf(a0, w.y, acc0.y); acc1.y = fmaf(a1, w.y, acc1.y);
        acc2.y = fmaf(a2, w.y, acc2.y); acc3.y = fmaf(a3, w.y, acc3.y);
        acc0.z = fmaf(a0, w.z, acc0.z); acc1.z = fmaf(a1, w.z, acc1.z);
        acc2.z = fmaf(a2, w.z, acc2.z); acc3.z = fmaf(a3, w.z, acc3.z);
        acc0.w = fmaf(a0, w.w, acc0.w); acc1.w = fmaf(a1, w.w, acc1.w);
        acc2.w = fmaf(a2, w.w, acc2.w); acc3.w = fmaf(a3, w.w, acc3.w);
    }

    if (relu) {
        acc0.x = fmaxf(acc0.x, 0.f); acc0.y = fmaxf(acc0.y, 0.f);
        acc0.z = fmaxf(acc0.z, 0.f); acc0.w = fmaxf(acc0.w, 0.f);
        acc1.x = fmaxf(acc1.x, 0.f); acc1.y = fmaxf(acc1.y, 0.f);
        acc1.z = fmaxf(acc1.z, 0.f); acc1.w = fmaxf(acc1.w, 0.f);
        acc2.x = fmaxf(acc2.x, 0.f); acc2.y = fmaxf(acc2.y, 0.f);
        acc2.z = fmaxf(acc2.z, 0.f); acc2.w = fmaxf(acc2.w, 0.f);
        acc3.x = fmaxf(acc3.x, 0.f); acc3.y = fmaxf(acc3.y, 0.f);
        acc3.z = fmaxf(acc3.z, 0.f); acc3.w = fmaxf(acc3.w, 0.f);
    }
    *(float4*)(out + (nodeBase + n0 + 0) * 64 + j0) = acc0;
    *(float4*)(out + (nodeBase + n0 + 1) * 64 + j0) = acc1;
    *(float4*)(out + (nodeBase + n0 + 2) * 64 + j0) = acc2;
    *(float4*)(out + (nodeBase + n0 + 3) * 64 + j0) = acc3;
}

// ---------------------------------------------------------------------------
// Fused pool+head: one block per graph. 256 threads = 64 dims x 4 node-lanes.
// pooled = mean over nodes; out[g][c] = b_lin[c] + pooled . w_lin[c].
__global__ void poolhead_kernel(const float* __restrict__ w_lin,
                                const float* __restrict__ b_lin,
                                float* __restrict__ out) {
    __shared__ float sred[256];
    __shared__ float sp[64];
    int g = blockIdx.x;
    int tid = threadIdx.x;
    int d = tid & 63;
    int r = tid >> 6;
    int start = g_bnd[g];
    int end = g_bnd[g + 1];

    float acc = 0.f;
    for (int n = start + r; n < end; n += 4)
        acc += g_h1[n * HD + d];
    sred[tid] = acc;
    __syncthreads();
    if (tid < 64)
        sp[tid] = sred[tid] + sred[tid + 64] + sred[tid + 128] + sred[tid + 192];
    __syncthreads();

    if (tid < NCLS) {
        float inv = 1.f / fmaxf((float)(end - start), 1.f);
        float a = 0.f;
#pragma unroll 8
        for (int k = 0; k < HD; k++)
            a += sp[k] * w_lin[tid * HD + k];
        out[g * NCLS + tid] = b_lin[tid] + a * inv;
    }
}

// ---------------------------------------------------------------------------
extern "C" void kernel_launch(void* const* d_in, const int* in_sizes, int n_in,
                              void* d_out, int out_size) {
    (void)in_sizes; (void)n_in; (void)out_size;
    const float* x = (const float*)d_in[0];
    const int* ei = (const int*)d_in[1];      // int32
    const int* batch = (const int*)d_in[2];   // int32
    const float* wr1 = (const float*)d_in[3];
    const float* br1 = (const float*)d_in[4];
    const float* wo1 = (const float*)d_in[5];
    const float* wr2 = (const float*)d_in[6];
    const float* br2 = (const float*)d_in[7];
    const float* wo2 = (const float*)d_in[8];
    const float* wr3 = (const float*)d_in[9];
    const float* br3 = (const float*)d_in[10];
    const float* wo3 = (const float*)d_in[11];
    const float* w_lin = (const float*)d_in[12];
    const float* b_lin = (const float*)d_in[13];
    float* out = (float*)d_out;

    const int eblocks = (EE + 255) / 256;
    const int fblocks = NN / 64;  // 1250

    // CSR build + graph boundaries
    zero_deg_kernel<<<(SCAN_BLKS * 1024 + 255) / 256, 256>>>();
    hist_kernel<<<eblocks, 256>>>(ei);
    bnd_kernel<<<3, 256>>>(batch);
    scan1_kernel<<<SCAN_BLKS, 256>>>();
    scan2_kernel<<<1, 128>>>();
    scan3_kernel<<<SCAN_BLKS, 256>>>();
    fill_kernel<<<eblocks, 256>>>(ei);

    // Fused gather+dense layers
    fused_layer_kernel<<<fblocks, 256>>>(0, x, 1, wr1, br1, wo1, 1);
    fused_layer_kernel<<<fblocks, 256>>>(1, x, 2, wr2, br2, wo2, 1);
    fused_layer_kernel<<<fblocks, 256>>>(2, x, 1, wr3, br3, wo3, 0);

    // Fused pool+head
    poolhead_kernel<<<GG, 256>>>(w_lin, b_lin, out);
}